// round 2
// baseline (speedup 1.0000x reference)
#include <cuda_runtime.h>
#include <cstdint>

// Problem shape (fixed by the dataset):
//   h   [N=100000, IN=256] f32
//   W   [OUT=128, IN=256]  f32
//   src [E=1600000] int (declared int64 in reference; harness may store int32)
//   dst [E=1600000] int
//   out [N, OUT=128] f32 = segment_mean( (h @ W^T)[src], dst )

#define IN_F  256
#define OUT_F 128
#define MAX_NODES 100000

// Scratch (static device globals — no runtime allocation allowed)
__device__ float g_z[(size_t)MAX_NODES * OUT_F];   // 51.2 MB projected features
__device__ float g_deg[MAX_NODES];                 // in-degree accumulator
__device__ int   g_idx_is64;                       // 1 if edge indices are int64

// ---------------------------------------------------------------------------
// Kernel -1: detect index dtype. int64 indices < 100000 -> high word always 0.
// int32 data read as u64 has high word = the following index (virtually never
// 0 sixteen times in a row).
// ---------------------------------------------------------------------------
__global__ void detect_kernel(const unsigned long long* __restrict__ s64, int E) {
    int n = E < 16 ? E : 16;
    int is64 = 1;
    for (int i = 0; i < n; i++)
        if ((s64[i] >> 32) != 0ull) { is64 = 0; break; }
    g_idx_is64 = is64;
}

// ---------------------------------------------------------------------------
// Kernel 0: zero the output accumulator (d_out is poisoned) and the degrees
// ---------------------------------------------------------------------------
__global__ void zero_kernel(float4* __restrict__ out4, int n4, int n_nodes) {
    int i = blockIdx.x * blockDim.x + threadIdx.x;
    if (i < n4) out4[i] = make_float4(0.f, 0.f, 0.f, 0.f);
    if (i < n_nodes) g_deg[i] = 0.f;
}

// ---------------------------------------------------------------------------
// Kernel 1: z = h @ W^T   (M x 256 @ 256 x 128)
// Tiled SIMT fp32 GEMM: BM=64, BN=128, BK=16, 256 threads, 8x4 per thread.
// ---------------------------------------------------------------------------
#define BM 64
#define BN 128
#define BK 16

__global__ __launch_bounds__(256)
void gemm_kernel(const float* __restrict__ h, const float* __restrict__ W,
                 float* __restrict__ z, int M) {
    __shared__ float As[BK][BM];
    __shared__ float Bs[BK][BN];

    const int tid = threadIdx.x;
    const int tx  = tid & 31;        // 0..31 -> 4 output cols each
    const int ty  = tid >> 5;        // 0..7  -> 8 output rows each
    const int rowBase = blockIdx.x * BM;

    const int aRow = tid >> 2;           // 0..63
    const int aCol = (tid & 3) * 4;      // 0,4,8,12

    float acc[8][4] = {};

    for (int k0 = 0; k0 < IN_F; k0 += BK) {
        float4 av = make_float4(0.f, 0.f, 0.f, 0.f);
        int gr = rowBase + aRow;
        if (gr < M)
            av = *reinterpret_cast<const float4*>(h + (size_t)gr * IN_F + k0 + aCol);
        As[aCol + 0][aRow] = av.x;
        As[aCol + 1][aRow] = av.y;
        As[aCol + 2][aRow] = av.z;
        As[aCol + 3][aRow] = av.w;

        #pragma unroll
        for (int r = 0; r < 2; r++) {
            int br = aRow + r * 64;      // 0..127
            float4 bv = *reinterpret_cast<const float4*>(W + (size_t)br * IN_F + k0 + aCol);
            Bs[aCol + 0][br] = bv.x;
            Bs[aCol + 1][br] = bv.y;
            Bs[aCol + 2][br] = bv.z;
            Bs[aCol + 3][br] = bv.w;
        }
        __syncthreads();

        #pragma unroll
        for (int kk = 0; kk < BK; kk++) {
            float4 a0 = *reinterpret_cast<float4*>(&As[kk][ty * 8]);
            float4 a1 = *reinterpret_cast<float4*>(&As[kk][ty * 8 + 4]);
            float4 b  = *reinterpret_cast<float4*>(&Bs[kk][tx * 4]);
            float a[8] = {a0.x, a0.y, a0.z, a0.w, a1.x, a1.y, a1.z, a1.w};
            #pragma unroll
            for (int i = 0; i < 8; i++) {
                acc[i][0] += a[i] * b.x;
                acc[i][1] += a[i] * b.y;
                acc[i][2] += a[i] * b.z;
                acc[i][3] += a[i] * b.w;
            }
        }
        __syncthreads();
    }

    #pragma unroll
    for (int i = 0; i < 8; i++) {
        int gr = rowBase + ty * 8 + i;
        if (gr < M) {
            float4 v = make_float4(acc[i][0], acc[i][1], acc[i][2], acc[i][3]);
            *reinterpret_cast<float4*>(z + (size_t)gr * OUT_F + tx * 4) = v;
        }
    }
}

// ---------------------------------------------------------------------------
// Kernel 2: edge scatter. One warp per edge; each lane moves 4 floats with a
// vectorized global reduction (red.global.add.v4.f32). Lane 0 bumps degree.
// Index dtype resolved at runtime via g_idx_is64; OOB indices are skipped
// (turns a would-be crash into a diagnosable wrong answer).
// ---------------------------------------------------------------------------
__global__ __launch_bounds__(256)
void scatter_kernel(const float* __restrict__ z,
                    const void* __restrict__ src_raw,
                    const void* __restrict__ dst_raw,
                    float* __restrict__ out, int E, int M) {
    int gtid = blockIdx.x * blockDim.x + threadIdx.x;
    int eid  = gtid >> 5;
    int lane = gtid & 31;
    if (eid >= E) return;

    const int is64 = g_idx_is64;   // uniform, L2/L1 cached
    long long s, d;
    if (is64) {
        s = ((const long long*)src_raw)[eid];
        d = ((const long long*)dst_raw)[eid];
    } else {
        s = ((const int*)src_raw)[eid];
        d = ((const int*)dst_raw)[eid];
    }
    if ((unsigned long long)s >= (unsigned long long)M ||
        (unsigned long long)d >= (unsigned long long)M) return;

    float4 v = *reinterpret_cast<const float4*>(z + (size_t)s * OUT_F + lane * 4);
    float* p = out + (size_t)d * OUT_F + lane * 4;
    asm volatile("red.global.add.v4.f32 [%0], {%1, %2, %3, %4};"
                 :: "l"(p), "f"(v.x), "f"(v.y), "f"(v.z), "f"(v.w)
                 : "memory");

    if (lane == 0) atomicAdd(&g_deg[(int)d], 1.0f);
}

// ---------------------------------------------------------------------------
// Kernel 3: out /= max(deg, 1)
// ---------------------------------------------------------------------------
__global__ __launch_bounds__(256)
void divide_kernel(float4* __restrict__ out4, int M) {
    int t = blockIdx.x * blockDim.x + threadIdx.x;   // one float4 per thread
    if (t >= M * (OUT_F / 4)) return;
    int node = t >> 5;                                // 32 float4 per node
    float inv = 1.0f / fmaxf(g_deg[node], 1.0f);
    float4 v = out4[t];
    v.x *= inv; v.y *= inv; v.z *= inv; v.w *= inv;
    out4[t] = v;
}

// ---------------------------------------------------------------------------
extern "C" void kernel_launch(void* const* d_in, const int* in_sizes, int n_in,
                              void* d_out, int out_size) {
    const float* h   = (const float*)d_in[0];
    const float* W   = (const float*)d_in[1];
    const void*  src = d_in[2];
    const void*  dst = d_in[3];
    float* out = (float*)d_out;

    const int M = in_sizes[0] / IN_F;      // 100000
    const int E = in_sizes[2];             // 1600000

    float* z;
    cudaGetSymbolAddress((void**)&z, g_z);

    // -1) detect index dtype (reads at most 16 u64 = 128 bytes, in-bounds
    //     for both int32 (E>=32) and int64 layouts)
    detect_kernel<<<1, 1>>>((const unsigned long long*)src, E);

    // 0) zero accumulators
    {
        int n4 = M * (OUT_F / 4);          // 3.2M float4
        int blocks = (n4 + 255) / 256;
        zero_kernel<<<blocks, 256>>>((float4*)out, n4, M);
    }
    // 1) z = h @ W^T
    {
        int blocks = (M + BM - 1) / BM;    // 1563
        gemm_kernel<<<blocks, 256>>>(h, W, z, M);
    }
    // 2) scatter-add per edge
    {
        long long threads = (long long)E * 32;
        int blocks = (int)((threads + 255) / 256);   // 200000
        scatter_kernel<<<blocks, 256>>>(z, src, dst, out, E, M);
    }
    // 3) mean
    {
        int n4 = M * (OUT_F / 4);
        int blocks = (n4 + 255) / 256;
        divide_kernel<<<blocks, 256>>>((float4*)out, M);
    }
}

// round 3
// speedup vs baseline: 1.5218x; 1.5218x over previous
#include <cuda_runtime.h>
#include <cstdint>

// Problem shape (fixed by the dataset):
//   h   [N=100000, IN=256] f32
//   W   [OUT=128, IN=256]  f32
//   src [E=1600000] indices (int32 or int64 on device; detected at runtime)
//   dst [E=1600000] indices
//   out [N, OUT=128] f32 = segment_mean( (h @ W^T)[src], dst )

#define IN_F  256
#define OUT_F 128
#define MAX_NODES 100000
#define MAX_EDGES 1600000
#define SCAN_BLK  1024

// Scratch (static device globals — no runtime allocation allowed)
__device__ float g_z[(size_t)MAX_NODES * OUT_F];   // 51.2 MB projected features
__device__ int   g_count[MAX_NODES];               // in-degree (int)
__device__ int   g_off[MAX_NODES];                 // CSR offsets (exclusive scan)
__device__ int   g_cur[MAX_NODES];                 // fill cursors
__device__ int   g_srcs[MAX_EDGES];                // src node per CSR slot
__device__ int   g_blksum[(MAX_NODES + SCAN_BLK - 1) / SCAN_BLK + 1];
__device__ int   g_idx_is64;                       // 1 if edge indices are int64

// ---------------------------------------------------------------------------
// Index dtype detect: int64 indices < 100000 -> high word always 0.
// ---------------------------------------------------------------------------
__global__ void detect_kernel(const unsigned long long* __restrict__ s64, int E) {
    int n = E < 16 ? E : 16;
    int is64 = 1;
    for (int i = 0; i < n; i++)
        if ((s64[i] >> 32) != 0ull) { is64 = 0; break; }
    g_idx_is64 = is64;
}

__device__ __forceinline__ int load_idx(const void* p, int i) {
    if (g_idx_is64) return (int)((const long long*)p)[i];
    return ((const int*)p)[i];
}

// ---------------------------------------------------------------------------
// Zero counters + cursors
// ---------------------------------------------------------------------------
__global__ void zero_kernel(int n_nodes) {
    int i = blockIdx.x * blockDim.x + threadIdx.x;
    if (i < n_nodes) { g_count[i] = 0; g_cur[i] = 0; }
}

// ---------------------------------------------------------------------------
// Degree histogram over dst
// ---------------------------------------------------------------------------
__global__ __launch_bounds__(256)
void hist_kernel(const void* __restrict__ dst, int E, int M) {
    int e = blockIdx.x * blockDim.x + threadIdx.x;
    if (e >= E) return;
    int d = load_idx(dst, e);
    if ((unsigned)d < (unsigned)M) atomicAdd(&g_count[d], 1);
}

// ---------------------------------------------------------------------------
// 3-stage exclusive scan of g_count -> g_off
// ---------------------------------------------------------------------------
__global__ __launch_bounds__(SCAN_BLK)
void scan1_kernel(int n) {
    __shared__ int sh[SCAN_BLK];
    int gid = blockIdx.x * SCAN_BLK + threadIdx.x;
    int v = (gid < n) ? g_count[gid] : 0;
    sh[threadIdx.x] = v;
    __syncthreads();
    // Hillis-Steele inclusive scan
    #pragma unroll
    for (int s = 1; s < SCAN_BLK; s <<= 1) {
        int t = (threadIdx.x >= s) ? sh[threadIdx.x - s] : 0;
        __syncthreads();
        sh[threadIdx.x] += t;
        __syncthreads();
    }
    if (gid < n) g_off[gid] = sh[threadIdx.x] - v;   // exclusive
    if (threadIdx.x == SCAN_BLK - 1) g_blksum[blockIdx.x] = sh[threadIdx.x];
}

__global__ void scan2_kernel(int nblocks) {
    // single thread: exclusive scan of per-block sums (<=98 values)
    int run = 0;
    for (int i = 0; i < nblocks; i++) {
        int v = g_blksum[i];
        g_blksum[i] = run;
        run += v;
    }
}

__global__ __launch_bounds__(SCAN_BLK)
void scan3_kernel(int n) {
    int gid = blockIdx.x * SCAN_BLK + threadIdx.x;
    if (gid < n) g_off[gid] += g_blksum[blockIdx.x];
}

// ---------------------------------------------------------------------------
// Fill CSR: write src node id into its dst bucket
// ---------------------------------------------------------------------------
__global__ __launch_bounds__(256)
void fill_kernel(const void* __restrict__ src, const void* __restrict__ dst,
                 int E, int M) {
    int e = blockIdx.x * blockDim.x + threadIdx.x;
    if (e >= E) return;
    int s = load_idx(src, e);
    int d = load_idx(dst, e);
    if ((unsigned)s >= (unsigned)M || (unsigned)d >= (unsigned)M) return;
    int slot = g_off[d] + atomicAdd(&g_cur[d], 1);
    g_srcs[slot] = s;
}

// ---------------------------------------------------------------------------
// Pull-aggregate: one warp per dst node. Sum z rows of its in-neighbors,
// divide by max(deg,1), store. No atomics on the fat path.
// ---------------------------------------------------------------------------
__global__ __launch_bounds__(256)
void gather_kernel(const float* __restrict__ z, float* __restrict__ out, int M) {
    int gtid = blockIdx.x * blockDim.x + threadIdx.x;
    int node = gtid >> 5;
    int lane = gtid & 31;
    if (node >= M) return;

    int beg = g_off[node];
    int cnt = g_count[node];

    float4 acc0 = make_float4(0.f, 0.f, 0.f, 0.f);
    float4 acc1 = make_float4(0.f, 0.f, 0.f, 0.f);

    int i = 0;
    // unroll-by-2: two independent dependency chains to expose MLP
    for (; i + 2 <= cnt; i += 2) {
        int s0 = g_srcs[beg + i];
        int s1 = g_srcs[beg + i + 1];
        float4 v0 = *reinterpret_cast<const float4*>(z + (size_t)s0 * OUT_F + lane * 4);
        float4 v1 = *reinterpret_cast<const float4*>(z + (size_t)s1 * OUT_F + lane * 4);
        acc0.x += v0.x; acc0.y += v0.y; acc0.z += v0.z; acc0.w += v0.w;
        acc1.x += v1.x; acc1.y += v1.y; acc1.z += v1.z; acc1.w += v1.w;
    }
    if (i < cnt) {
        int s0 = g_srcs[beg + i];
        float4 v0 = *reinterpret_cast<const float4*>(z + (size_t)s0 * OUT_F + lane * 4);
        acc0.x += v0.x; acc0.y += v0.y; acc0.z += v0.z; acc0.w += v0.w;
    }

    float inv = 1.0f / (float)(cnt > 0 ? cnt : 1);
    float4 r;
    r.x = (acc0.x + acc1.x) * inv;
    r.y = (acc0.y + acc1.y) * inv;
    r.z = (acc0.z + acc1.z) * inv;
    r.w = (acc0.w + acc1.w) * inv;
    *reinterpret_cast<float4*>(out + (size_t)node * OUT_F + lane * 4) = r;
}

// ---------------------------------------------------------------------------
// z = h @ W^T   (M x 256 @ 256 x 128) — tiled SIMT fp32 GEMM (unchanged)
// ---------------------------------------------------------------------------
#define BM 64
#define BN 128
#define BK 16

__global__ __launch_bounds__(256)
void gemm_kernel(const float* __restrict__ h, const float* __restrict__ W,
                 float* __restrict__ z, int M) {
    __shared__ float As[BK][BM];
    __shared__ float Bs[BK][BN];

    const int tid = threadIdx.x;
    const int tx  = tid & 31;
    const int ty  = tid >> 5;
    const int rowBase = blockIdx.x * BM;

    const int aRow = tid >> 2;
    const int aCol = (tid & 3) * 4;

    float acc[8][4] = {};

    for (int k0 = 0; k0 < IN_F; k0 += BK) {
        float4 av = make_float4(0.f, 0.f, 0.f, 0.f);
        int gr = rowBase + aRow;
        if (gr < M)
            av = *reinterpret_cast<const float4*>(h + (size_t)gr * IN_F + k0 + aCol);
        As[aCol + 0][aRow] = av.x;
        As[aCol + 1][aRow] = av.y;
        As[aCol + 2][aRow] = av.z;
        As[aCol + 3][aRow] = av.w;

        #pragma unroll
        for (int r = 0; r < 2; r++) {
            int br = aRow + r * 64;
            float4 bv = *reinterpret_cast<const float4*>(W + (size_t)br * IN_F + k0 + aCol);
            Bs[aCol + 0][br] = bv.x;
            Bs[aCol + 1][br] = bv.y;
            Bs[aCol + 2][br] = bv.z;
            Bs[aCol + 3][br] = bv.w;
        }
        __syncthreads();

        #pragma unroll
        for (int kk = 0; kk < BK; kk++) {
            float4 a0 = *reinterpret_cast<float4*>(&As[kk][ty * 8]);
            float4 a1 = *reinterpret_cast<float4*>(&As[kk][ty * 8 + 4]);
            float4 b  = *reinterpret_cast<float4*>(&Bs[kk][tx * 4]);
            float a[8] = {a0.x, a0.y, a0.z, a0.w, a1.x, a1.y, a1.z, a1.w};
            #pragma unroll
            for (int i = 0; i < 8; i++) {
                acc[i][0] += a[i] * b.x;
                acc[i][1] += a[i] * b.y;
                acc[i][2] += a[i] * b.z;
                acc[i][3] += a[i] * b.w;
            }
        }
        __syncthreads();
    }

    #pragma unroll
    for (int i = 0; i < 8; i++) {
        int gr = rowBase + ty * 8 + i;
        if (gr < M) {
            float4 v = make_float4(acc[i][0], acc[i][1], acc[i][2], acc[i][3]);
            *reinterpret_cast<float4*>(z + (size_t)gr * OUT_F + tx * 4) = v;
        }
    }
}

// ---------------------------------------------------------------------------
extern "C" void kernel_launch(void* const* d_in, const int* in_sizes, int n_in,
                              void* d_out, int out_size) {
    const float* h   = (const float*)d_in[0];
    const float* W   = (const float*)d_in[1];
    const void*  src = d_in[2];
    const void*  dst = d_in[3];
    float* out = (float*)d_out;

    const int M = in_sizes[0] / IN_F;      // 100000
    const int E = in_sizes[2];             // 1600000

    float* z;
    cudaGetSymbolAddress((void**)&z, g_z);

    const int scan_blocks = (M + SCAN_BLK - 1) / SCAN_BLK;   // 98
    const int eb = (E + 255) / 256;                          // 6250

    // dtype detect + zero counters (independent of GEMM)
    detect_kernel<<<1, 1>>>((const unsigned long long*)src, E);
    zero_kernel<<<(M + 255) / 256, 256>>>(M);

    // CSR build
    hist_kernel<<<eb, 256>>>(dst, E, M);
    scan1_kernel<<<scan_blocks, SCAN_BLK>>>(M);
    scan2_kernel<<<1, 1>>>(scan_blocks);
    scan3_kernel<<<scan_blocks, SCAN_BLK>>>(M);
    fill_kernel<<<eb, 256>>>(src, dst, E, M);

    // GEMM (independent of CSR build; stream order fine)
    gemm_kernel<<<(M + BM - 1) / BM, 256>>>(h, W, z, M);

    // Pull aggregation + mean (one warp per node)
    {
        long long threads = (long long)M * 32;
        int blocks = (int)((threads + 255) / 256);   // 12500
        gather_kernel<<<blocks, 256>>>(z, out, M);
    }
}

// round 4
// speedup vs baseline: 1.9615x; 1.2889x over previous
#include <cuda_runtime.h>
#include <cuda_bf16.h>
#include <cstdint>

// GCN layer: out = segment_mean( (h @ W^T)[src], dst )
//   h   [N=100000, IN=256] f32
//   W   [OUT=128, IN=256]  f32
//   src/dst [E=1600000] indices (int32 or int64 on device; detected at runtime)

#define IN_F  256
#define OUT_F 128
#define MAX_NODES 100000
#define MAX_EDGES 1600000
#define SCAN_BLK  1024

// Scratch (static device globals — no runtime allocation allowed)
__device__ float g_z[(size_t)MAX_NODES * OUT_F];   // 51.2 MB projected features
__device__ int   g_count[MAX_NODES];
__device__ int   g_off[MAX_NODES];
__device__ int   g_cur[MAX_NODES];
__device__ int   g_srcs[MAX_EDGES];
__device__ int   g_blksum[(MAX_NODES + SCAN_BLK - 1) / SCAN_BLK + 1];
__device__ int   g_idx_is64;

// ---------------------------------------------------------------------------
__global__ void detect_kernel(const unsigned long long* __restrict__ s64, int E) {
    int n = E < 16 ? E : 16;
    int is64 = 1;
    for (int i = 0; i < n; i++)
        if ((s64[i] >> 32) != 0ull) { is64 = 0; break; }
    g_idx_is64 = is64;
}

__device__ __forceinline__ int load_idx(const void* p, int i) {
    if (g_idx_is64) return (int)((const long long*)p)[i];
    return ((const int*)p)[i];
}

__global__ void zero_kernel(int n_nodes) {
    int i = blockIdx.x * blockDim.x + threadIdx.x;
    if (i < n_nodes) { g_count[i] = 0; g_cur[i] = 0; }
}

__global__ __launch_bounds__(256)
void hist_kernel(const void* __restrict__ dst, int E, int M) {
    int e = blockIdx.x * blockDim.x + threadIdx.x;
    if (e >= E) return;
    int d = load_idx(dst, e);
    if ((unsigned)d < (unsigned)M) atomicAdd(&g_count[d], 1);
}

__global__ __launch_bounds__(SCAN_BLK)
void scan1_kernel(int n) {
    __shared__ int sh[SCAN_BLK];
    int gid = blockIdx.x * SCAN_BLK + threadIdx.x;
    int v = (gid < n) ? g_count[gid] : 0;
    sh[threadIdx.x] = v;
    __syncthreads();
    #pragma unroll
    for (int s = 1; s < SCAN_BLK; s <<= 1) {
        int t = (threadIdx.x >= s) ? sh[threadIdx.x - s] : 0;
        __syncthreads();
        sh[threadIdx.x] += t;
        __syncthreads();
    }
    if (gid < n) g_off[gid] = sh[threadIdx.x] - v;
    if (threadIdx.x == SCAN_BLK - 1) g_blksum[blockIdx.x] = sh[threadIdx.x];
}

__global__ void scan2_kernel(int nblocks) {
    int run = 0;
    for (int i = 0; i < nblocks; i++) {
        int v = g_blksum[i];
        g_blksum[i] = run;
        run += v;
    }
}

__global__ __launch_bounds__(SCAN_BLK)
void scan3_kernel(int n) {
    int gid = blockIdx.x * SCAN_BLK + threadIdx.x;
    if (gid < n) g_off[gid] += g_blksum[blockIdx.x];
}

__global__ __launch_bounds__(256)
void fill_kernel(const void* __restrict__ src, const void* __restrict__ dst,
                 int E, int M) {
    int e = blockIdx.x * blockDim.x + threadIdx.x;
    if (e >= E) return;
    int s = load_idx(src, e);
    int d = load_idx(dst, e);
    if ((unsigned)s >= (unsigned)M || (unsigned)d >= (unsigned)M) return;
    int slot = g_off[d] + atomicAdd(&g_cur[d], 1);
    g_srcs[slot] = s;
}

// ---------------------------------------------------------------------------
// Pull-aggregate: one warp per dst node (unchanged, passed R2).
// ---------------------------------------------------------------------------
__global__ __launch_bounds__(256)
void gather_kernel(const float* __restrict__ z, float* __restrict__ out, int M) {
    int gtid = blockIdx.x * blockDim.x + threadIdx.x;
    int node = gtid >> 5;
    int lane = gtid & 31;
    if (node >= M) return;

    int beg = g_off[node];
    int cnt = g_count[node];

    float4 acc0 = make_float4(0.f, 0.f, 0.f, 0.f);
    float4 acc1 = make_float4(0.f, 0.f, 0.f, 0.f);

    int i = 0;
    for (; i + 2 <= cnt; i += 2) {
        int s0 = g_srcs[beg + i];
        int s1 = g_srcs[beg + i + 1];
        float4 v0 = *reinterpret_cast<const float4*>(z + (size_t)s0 * OUT_F + lane * 4);
        float4 v1 = *reinterpret_cast<const float4*>(z + (size_t)s1 * OUT_F + lane * 4);
        acc0.x += v0.x; acc0.y += v0.y; acc0.z += v0.z; acc0.w += v0.w;
        acc1.x += v1.x; acc1.y += v1.y; acc1.z += v1.z; acc1.w += v1.w;
    }
    if (i < cnt) {
        int s0 = g_srcs[beg + i];
        float4 v0 = *reinterpret_cast<const float4*>(z + (size_t)s0 * OUT_F + lane * 4);
        acc0.x += v0.x; acc0.y += v0.y; acc0.z += v0.z; acc0.w += v0.w;
    }

    float inv = 1.0f / (float)(cnt > 0 ? cnt : 1);
    float4 r;
    r.x = (acc0.x + acc1.x) * inv;
    r.y = (acc0.y + acc1.y) * inv;
    r.z = (acc0.z + acc1.z) * inv;
    r.w = (acc0.w + acc1.w) * inv;
    *reinterpret_cast<float4*>(out + (size_t)node * OUT_F + lane * 4) = r;
}

// ---------------------------------------------------------------------------
// Tensor-core GEMM: z = h @ W^T via bf16 split-3 HMMA (mma.sync.m16n8k16).
//   a = a_hi + a_lo (bf16 RN split);  acc += ahi*bhi + ahi*blo + alo*bhi
//   dropped alo*blo term ~2^-18 relative.
// Block: 128(M) x 128(N), 8 warps (4x2), warp tile 32x64, K-chunk 32.
// smem bf16 tiles padded to 40-element rows (80B) -> conflict-free LDSM.
// ---------------------------------------------------------------------------
#define GBK 32
#define SPAD 40   // padded bf16 row stride (elements)

__device__ __forceinline__ void ldsm_x4(unsigned r[4], unsigned saddr) {
    asm volatile("ldmatrix.sync.aligned.m8n8.x4.shared.b16 {%0,%1,%2,%3}, [%4];"
                 : "=r"(r[0]), "=r"(r[1]), "=r"(r[2]), "=r"(r[3]) : "r"(saddr));
}
__device__ __forceinline__ void ldsm_x2(unsigned r[2], unsigned saddr) {
    asm volatile("ldmatrix.sync.aligned.m8n8.x2.shared.b16 {%0,%1}, [%2];"
                 : "=r"(r[0]), "=r"(r[1]) : "r"(saddr));
}
__device__ __forceinline__ void mma_bf16(float c[4], const unsigned a[4],
                                         const unsigned b[2]) {
    asm volatile("mma.sync.aligned.m16n8k16.row.col.f32.bf16.bf16.f32 "
                 "{%0,%1,%2,%3}, {%4,%5,%6,%7}, {%8,%9}, {%0,%1,%2,%3};"
                 : "+f"(c[0]), "+f"(c[1]), "+f"(c[2]), "+f"(c[3])
                 : "r"(a[0]), "r"(a[1]), "r"(a[2]), "r"(a[3]),
                   "r"(b[0]), "r"(b[1]));
}

__device__ __forceinline__ unsigned pack_bf16x2(__nv_bfloat16 lo, __nv_bfloat16 hi) {
    unsigned short l = __bfloat16_as_ushort(lo);
    unsigned short h = __bfloat16_as_ushort(hi);
    return (unsigned)l | ((unsigned)h << 16);
}

__global__ __launch_bounds__(256)
void gemm_tc_kernel(const float* __restrict__ h, const float* __restrict__ W,
                    float* __restrict__ z, int M) {
    __shared__ __align__(16) __nv_bfloat16 sAhi[128 * SPAD];
    __shared__ __align__(16) __nv_bfloat16 sAlo[128 * SPAD];
    __shared__ __align__(16) __nv_bfloat16 sBhi[128 * SPAD];
    __shared__ __align__(16) __nv_bfloat16 sBlo[128 * SPAD];

    const int tid  = threadIdx.x;
    const int warp = tid >> 5;
    const int lane = tid & 31;
    const int wm   = warp & 3;     // M quadrant (0..3) -> 32 rows
    const int wn   = warp >> 2;    // N half (0..1)     -> 64 cols
    const int rowBase = blockIdx.x * 128;

    const unsigned uAhi = (unsigned)__cvta_generic_to_shared(sAhi);
    const unsigned uAlo = (unsigned)__cvta_generic_to_shared(sAlo);
    const unsigned uBhi = (unsigned)__cvta_generic_to_shared(sBhi);
    const unsigned uBlo = (unsigned)__cvta_generic_to_shared(sBlo);

    float acc[2][8][4] = {};   // [m-tile 16][n-tile 8][c-frag]

    for (int k0 = 0; k0 < IN_F; k0 += GBK) {
        // --- stage + split-convert A (h rows) and B (W rows) ---
        #pragma unroll
        for (int it = 0; it < 4; it++) {
            int idx = tid + it * 256;          // 0..1023
            int r = idx >> 3;                  // 0..127
            int c = (idx & 7) * 4;             // 0..28
            // A
            float4 va = make_float4(0.f, 0.f, 0.f, 0.f);
            if (rowBase + r < M)
                va = *reinterpret_cast<const float4*>(h + (size_t)(rowBase + r) * IN_F + k0 + c);
            // B (always in-bounds: W is 128x256)
            float4 vb = *reinterpret_cast<const float4*>(W + (size_t)r * IN_F + k0 + c);

            __nv_bfloat16 ahx = __float2bfloat16(va.x), ahy = __float2bfloat16(va.y);
            __nv_bfloat16 ahz = __float2bfloat16(va.z), ahw = __float2bfloat16(va.w);
            __nv_bfloat16 alx = __float2bfloat16(va.x - __bfloat162float(ahx));
            __nv_bfloat16 aly = __float2bfloat16(va.y - __bfloat162float(ahy));
            __nv_bfloat16 alz = __float2bfloat16(va.z - __bfloat162float(ahz));
            __nv_bfloat16 alw = __float2bfloat16(va.w - __bfloat162float(ahw));
            __nv_bfloat16 bhx = __float2bfloat16(vb.x), bhy = __float2bfloat16(vb.y);
            __nv_bfloat16 bhz = __float2bfloat16(vb.z), bhw = __float2bfloat16(vb.w);
            __nv_bfloat16 blx = __float2bfloat16(vb.x - __bfloat162float(bhx));
            __nv_bfloat16 bly = __float2bfloat16(vb.y - __bfloat162float(bhy));
            __nv_bfloat16 blz = __float2bfloat16(vb.z - __bfloat162float(bhz));
            __nv_bfloat16 blw = __float2bfloat16(vb.w - __bfloat162float(bhw));

            int o = r * SPAD + c;
            *reinterpret_cast<uint2*>(&sAhi[o]) =
                make_uint2(pack_bf16x2(ahx, ahy), pack_bf16x2(ahz, ahw));
            *reinterpret_cast<uint2*>(&sAlo[o]) =
                make_uint2(pack_bf16x2(alx, aly), pack_bf16x2(alz, alw));
            *reinterpret_cast<uint2*>(&sBhi[o]) =
                make_uint2(pack_bf16x2(bhx, bhy), pack_bf16x2(bhz, bhw));
            *reinterpret_cast<uint2*>(&sBlo[o]) =
                make_uint2(pack_bf16x2(blx, bly), pack_bf16x2(blz, blw));
        }
        __syncthreads();

        // --- MMA over the 32-wide chunk, two k-steps of 16 ---
        #pragma unroll
        for (int ks = 0; ks < GBK; ks += 16) {
            // A fragments: row = warp 32-row quadrant + mt*16 + lane%16,
            //              col8 = +8 half for lanes >= 16 (ldmatrix x4 order
            //              == mma a0..a3 quadrant order)
            unsigned a_hi[2][4], a_lo[2][4];
            #pragma unroll
            for (int mt = 0; mt < 2; mt++) {
                int row = wm * 32 + mt * 16 + (lane & 15);
                int col = ks + ((lane >> 4) << 3);
                unsigned off = (unsigned)(row * SPAD + col) * 2u;
                ldsm_x4(a_hi[mt], uAhi + off);
                ldsm_x4(a_lo[mt], uAlo + off);
            }
            #pragma unroll
            for (int nt = 0; nt < 8; nt++) {
                // B fragment: smem [n][k] non-trans ldmatrix == col-major B frag
                int brow = wn * 64 + nt * 8 + (lane & 7);
                int bcol = ks + (lane & 8);
                unsigned off = (unsigned)(brow * SPAD + bcol) * 2u;
                unsigned b_hi[2], b_lo[2];
                ldsm_x2(b_hi, uBhi + off);
                ldsm_x2(b_lo, uBlo + off);
                #pragma unroll
                for (int mt = 0; mt < 2; mt++) {
                    mma_bf16(acc[mt][nt], a_hi[mt], b_hi);
                    mma_bf16(acc[mt][nt], a_hi[mt], b_lo);
                    mma_bf16(acc[mt][nt], a_lo[mt], b_hi);
                }
            }
        }
        __syncthreads();
    }

    // --- epilogue: c0,c1 -> (row g, col 2t..2t+1); c2,c3 -> row g+8 ---
    const int g   = lane >> 2;
    const int tig = lane & 3;
    #pragma unroll
    for (int mt = 0; mt < 2; mt++) {
        #pragma unroll
        for (int nt = 0; nt < 8; nt++) {
            int row0 = rowBase + wm * 32 + mt * 16 + g;
            int col  = wn * 64 + nt * 8 + tig * 2;
            if (row0 < M)
                *reinterpret_cast<float2*>(z + (size_t)row0 * OUT_F + col) =
                    make_float2(acc[mt][nt][0], acc[mt][nt][1]);
            int row1 = row0 + 8;
            if (row1 < M)
                *reinterpret_cast<float2*>(z + (size_t)row1 * OUT_F + col) =
                    make_float2(acc[mt][nt][2], acc[mt][nt][3]);
        }
    }
}

// ---------------------------------------------------------------------------
extern "C" void kernel_launch(void* const* d_in, const int* in_sizes, int n_in,
                              void* d_out, int out_size) {
    const float* h   = (const float*)d_in[0];
    const float* W   = (const float*)d_in[1];
    const void*  src = d_in[2];
    const void*  dst = d_in[3];
    float* out = (float*)d_out;

    const int M = in_sizes[0] / IN_F;      // 100000
    const int E = in_sizes[2];             // 1600000

    float* z;
    cudaGetSymbolAddress((void**)&z, g_z);

    const int scan_blocks = (M + SCAN_BLK - 1) / SCAN_BLK;   // 98
    const int eb = (E + 255) / 256;                          // 6250

    detect_kernel<<<1, 1>>>((const unsigned long long*)src, E);
    zero_kernel<<<(M + 255) / 256, 256>>>(M);

    // CSR build
    hist_kernel<<<eb, 256>>>(dst, E, M);
    scan1_kernel<<<scan_blocks, SCAN_BLK>>>(M);
    scan2_kernel<<<1, 1>>>(scan_blocks);
    scan3_kernel<<<scan_blocks, SCAN_BLK>>>(M);
    fill_kernel<<<eb, 256>>>(src, dst, E, M);

    // Tensor-core GEMM
    gemm_tc_kernel<<<(M + 127) / 128, 256>>>(h, W, z, M);

    // Pull aggregation + mean
    {
        long long threads = (long long)M * 32;
        int blocks = (int)((threads + 255) / 256);   // 12500
        gather_kernel<<<blocks, 256>>>(z, out, M);
    }
}

// round 5
// speedup vs baseline: 2.1232x; 1.0824x over previous
#include <cuda_runtime.h>
#include <cuda_bf16.h>
#include <cstdint>

// GCN layer: out = segment_mean( (h @ W^T)[src], dst )
//   h   [N=100000, IN=256] f32
//   W   [OUT=128, IN=256]  f32
//   src/dst [E=1600000] indices (int32 or int64 on device; detected at runtime)

#define IN_F  256
#define OUT_F 128
#define MAX_NODES 100000
#define MAX_EDGES 1600000
#define SCAN_BLK  1024

// Scratch (static device globals — no runtime allocation allowed)
__device__ float    g_z[(size_t)MAX_NODES * OUT_F];   // 51.2 MB projected features
__device__ int      g_count[MAX_NODES];
__device__ int      g_off[MAX_NODES];
__device__ int      g_cur[MAX_NODES];
__device__ int      g_srcs[MAX_EDGES];
__device__ int      g_blksum[(MAX_NODES + SCAN_BLK - 1) / SCAN_BLK + 1];
__device__ int      g_idx_is64;
__device__ unsigned g_Whi[OUT_F * IN_F / 2];          // W bf16 hi plane (packed x2)
__device__ unsigned g_Wlo[OUT_F * IN_F / 2];          // W bf16 lo plane (packed x2)

// ---------------------------------------------------------------------------
// Packed split helper: v -> bf16 hi pair + bf16 lo (residual) pair.
// cvt.rn.bf16x2.f32 d, a, b : d[31:16]=bf(a), d[15:0]=bf(b)
// ---------------------------------------------------------------------------
__device__ __forceinline__ void split4(float4 v, uint2& hi, uint2& lo) {
    unsigned hxy, hzw;
    asm("cvt.rn.bf16x2.f32 %0, %1, %2;" : "=r"(hxy) : "f"(v.y), "f"(v.x));
    asm("cvt.rn.bf16x2.f32 %0, %1, %2;" : "=r"(hzw) : "f"(v.w), "f"(v.z));
    float hx = __uint_as_float(hxy << 16);
    float hy = __uint_as_float(hxy & 0xFFFF0000u);
    float hz = __uint_as_float(hzw << 16);
    float hw = __uint_as_float(hzw & 0xFFFF0000u);
    unsigned lxy, lzw;
    asm("cvt.rn.bf16x2.f32 %0, %1, %2;" : "=r"(lxy) : "f"(v.y - hy), "f"(v.x - hx));
    asm("cvt.rn.bf16x2.f32 %0, %1, %2;" : "=r"(lzw) : "f"(v.w - hw), "f"(v.z - hz));
    hi = make_uint2(hxy, hzw);
    lo = make_uint2(lxy, lzw);
}

// ---------------------------------------------------------------------------
// prep: fused index-dtype detect + counter zero + W split-convert
// ---------------------------------------------------------------------------
__global__ __launch_bounds__(256)
void prep_kernel(const unsigned long long* __restrict__ s64, int E,
                 const float* __restrict__ W, int M) {
    int i = blockIdx.x * blockDim.x + threadIdx.x;
    if (i == 0) {
        int n = E < 16 ? E : 16;
        int is64 = 1;
        for (int j = 0; j < n; j++)
            if ((s64[j] >> 32) != 0ull) { is64 = 0; break; }
        g_idx_is64 = is64;
    }
    if (i < M) { g_count[i] = 0; g_cur[i] = 0; }
    if (i < OUT_F * IN_F / 4) {
        float4 v = *reinterpret_cast<const float4*>(W + (size_t)i * 4);
        uint2 hi, lo;
        split4(v, hi, lo);
        *reinterpret_cast<uint2*>(&g_Whi[i * 2]) = hi;
        *reinterpret_cast<uint2*>(&g_Wlo[i * 2]) = lo;
    }
}

__device__ __forceinline__ int load_idx(const void* p, int i) {
    if (g_idx_is64) return (int)((const long long*)p)[i];
    return ((const int*)p)[i];
}

__global__ __launch_bounds__(256)
void hist_kernel(const void* __restrict__ dst, int E, int M) {
    int e = blockIdx.x * blockDim.x + threadIdx.x;
    if (e >= E) return;
    int d = load_idx(dst, e);
    if ((unsigned)d < (unsigned)M) atomicAdd(&g_count[d], 1);
}

__global__ __launch_bounds__(SCAN_BLK)
void scan1_kernel(int n) {
    __shared__ int sh[SCAN_BLK];
    int gid = blockIdx.x * SCAN_BLK + threadIdx.x;
    int v = (gid < n) ? g_count[gid] : 0;
    sh[threadIdx.x] = v;
    __syncthreads();
    #pragma unroll
    for (int s = 1; s < SCAN_BLK; s <<= 1) {
        int t = (threadIdx.x >= s) ? sh[threadIdx.x - s] : 0;
        __syncthreads();
        sh[threadIdx.x] += t;
        __syncthreads();
    }
    if (gid < n) g_off[gid] = sh[threadIdx.x] - v;
    if (threadIdx.x == SCAN_BLK - 1) g_blksum[blockIdx.x] = sh[threadIdx.x];
}

__global__ void scan2_kernel(int nblocks) {
    int run = 0;
    for (int i = 0; i < nblocks; i++) {
        int v = g_blksum[i];
        g_blksum[i] = run;
        run += v;
    }
}

__global__ __launch_bounds__(SCAN_BLK)
void scan3_kernel(int n) {
    int gid = blockIdx.x * SCAN_BLK + threadIdx.x;
    if (gid < n) g_off[gid] += g_blksum[blockIdx.x];
}

__global__ __launch_bounds__(256)
void fill_kernel(const void* __restrict__ src, const void* __restrict__ dst,
                 int E, int M) {
    int e = blockIdx.x * blockDim.x + threadIdx.x;
    if (e >= E) return;
    int s = load_idx(src, e);
    int d = load_idx(dst, e);
    if ((unsigned)s >= (unsigned)M || (unsigned)d >= (unsigned)M) return;
    int slot = g_off[d] + atomicAdd(&g_cur[d], 1);
    g_srcs[slot] = s;
}

// ---------------------------------------------------------------------------
// Pull-aggregate: one warp per dst node (proven in R2-R4).
// ---------------------------------------------------------------------------
__global__ __launch_bounds__(256)
void gather_kernel(const float* __restrict__ z, float* __restrict__ out, int M) {
    int gtid = blockIdx.x * blockDim.x + threadIdx.x;
    int node = gtid >> 5;
    int lane = gtid & 31;
    if (node >= M) return;

    int beg = g_off[node];
    int cnt = g_count[node];

    float4 acc0 = make_float4(0.f, 0.f, 0.f, 0.f);
    float4 acc1 = make_float4(0.f, 0.f, 0.f, 0.f);

    int i = 0;
    for (; i + 2 <= cnt; i += 2) {
        int s0 = g_srcs[beg + i];
        int s1 = g_srcs[beg + i + 1];
        float4 v0 = *reinterpret_cast<const float4*>(z + (size_t)s0 * OUT_F + lane * 4);
        float4 v1 = *reinterpret_cast<const float4*>(z + (size_t)s1 * OUT_F + lane * 4);
        acc0.x += v0.x; acc0.y += v0.y; acc0.z += v0.z; acc0.w += v0.w;
        acc1.x += v1.x; acc1.y += v1.y; acc1.z += v1.z; acc1.w += v1.w;
    }
    if (i < cnt) {
        int s0 = g_srcs[beg + i];
        float4 v0 = *reinterpret_cast<const float4*>(z + (size_t)s0 * OUT_F + lane * 4);
        acc0.x += v0.x; acc0.y += v0.y; acc0.z += v0.z; acc0.w += v0.w;
    }

    float inv = 1.0f / (float)(cnt > 0 ? cnt : 1);
    float4 r;
    r.x = (acc0.x + acc1.x) * inv;
    r.y = (acc0.y + acc1.y) * inv;
    r.z = (acc0.z + acc1.z) * inv;
    r.w = (acc0.w + acc1.w) * inv;
    *reinterpret_cast<float4*>(out + (size_t)node * OUT_F + lane * 4) = r;
}

// ---------------------------------------------------------------------------
// Tensor-core GEMM: z = h @ W^T via bf16 split-3 HMMA (mma.sync.m16n8k16).
// Block 128x128, 8 warps (4x2), warp tile 32x64, K-chunk 32.
// B staged from pre-converted bf16 planes; A split in-kernel (packed cvt);
// next chunk's A prefetched into registers during MMA.
// ---------------------------------------------------------------------------
#define GBK 32
#define SPAD 40   // padded bf16 row stride (elements); 80B = 5*16B, uint4-safe

__device__ __forceinline__ void ldsm_x4(unsigned r[4], unsigned saddr) {
    asm volatile("ldmatrix.sync.aligned.m8n8.x4.shared.b16 {%0,%1,%2,%3}, [%4];"
                 : "=r"(r[0]), "=r"(r[1]), "=r"(r[2]), "=r"(r[3]) : "r"(saddr));
}
__device__ __forceinline__ void ldsm_x2(unsigned r[2], unsigned saddr) {
    asm volatile("ldmatrix.sync.aligned.m8n8.x2.shared.b16 {%0,%1}, [%2];"
                 : "=r"(r[0]), "=r"(r[1]) : "r"(saddr));
}
__device__ __forceinline__ void mma_bf16(float c[4], const unsigned a[4],
                                         const unsigned b[2]) {
    asm volatile("mma.sync.aligned.m16n8k16.row.col.f32.bf16.bf16.f32 "
                 "{%0,%1,%2,%3}, {%4,%5,%6,%7}, {%8,%9}, {%0,%1,%2,%3};"
                 : "+f"(c[0]), "+f"(c[1]), "+f"(c[2]), "+f"(c[3])
                 : "r"(a[0]), "r"(a[1]), "r"(a[2]), "r"(a[3]),
                   "r"(b[0]), "r"(b[1]));
}

__global__ __launch_bounds__(256)
void gemm_tc_kernel(const float* __restrict__ h, float* __restrict__ z, int M) {
    __shared__ __align__(16) __nv_bfloat16 sAhi[128 * SPAD];
    __shared__ __align__(16) __nv_bfloat16 sAlo[128 * SPAD];
    __shared__ __align__(16) __nv_bfloat16 sBhi[128 * SPAD];
    __shared__ __align__(16) __nv_bfloat16 sBlo[128 * SPAD];

    const int tid  = threadIdx.x;
    const int warp = tid >> 5;
    const int lane = tid & 31;
    const int wm   = warp & 3;     // M quadrant -> 32 rows
    const int wn   = warp >> 2;    // N half     -> 64 cols
    const int rowBase = blockIdx.x * 128;

    const unsigned uAhi = (unsigned)__cvta_generic_to_shared(sAhi);
    const unsigned uAlo = (unsigned)__cvta_generic_to_shared(sAlo);
    const unsigned uBhi = (unsigned)__cvta_generic_to_shared(sBhi);
    const unsigned uBlo = (unsigned)__cvta_generic_to_shared(sBlo);

    // A staging map: 4 float4 per thread covering 128 rows x 32 cols
    const int ar = tid >> 1;              // 0..127 (two threads per row)
    const int ac = (tid & 1) * 16;        // 0 or 16; each thread owns 4 consecutive float4
    const bool aval = (rowBase + ar) < M;
    const float* aptr = h + (size_t)(rowBase + ar) * IN_F + ac;

    // B staging map: 4 uint4 per thread per plane (8KB per plane per chunk)
    // plane layout: [128 rows][128 packed-bf16x2 words]; chunk k0 -> word col k0/2
    const int br = tid >> 1;              // 0..127
    const int bc = (tid & 1) * 8;         // word col 0 or 8 (16 bf16)

    float4 pf[4];                         // A prefetch registers
    #pragma unroll
    for (int q = 0; q < 4; q++)
        pf[q] = aval ? *reinterpret_cast<const float4*>(aptr + q * 4)
                     : make_float4(0.f, 0.f, 0.f, 0.f);

    float acc[2][8][4] = {};

    for (int k0 = 0; k0 < IN_F; k0 += GBK) {
        // --- stage A (from prefetch regs) ---
        #pragma unroll
        for (int q = 0; q < 4; q++) {
            uint2 hi, lo;
            split4(pf[q], hi, lo);
            int o = ar * SPAD + ac + q * 4;
            *reinterpret_cast<uint2*>(&sAhi[o]) = hi;
            *reinterpret_cast<uint2*>(&sAlo[o]) = lo;
        }
        // --- stage B (bf16 copy from pre-converted planes) ---
        {
            const unsigned* srcHi = &g_Whi[(size_t)br * (IN_F / 2) + k0 / 2 + bc];
            const unsigned* srcLo = &g_Wlo[(size_t)br * (IN_F / 2) + k0 / 2 + bc];
            uint4 vh = *reinterpret_cast<const uint4*>(srcHi);
            uint4 vl = *reinterpret_cast<const uint4*>(srcLo);
            uint4 vh2 = *reinterpret_cast<const uint4*>(srcHi + 4);
            uint4 vl2 = *reinterpret_cast<const uint4*>(srcLo + 4);
            int o = br * SPAD + bc * 2;
            *reinterpret_cast<uint4*>(&sBhi[o])     = vh;
            *reinterpret_cast<uint4*>(&sBhi[o + 8]) = vh2;
            *reinterpret_cast<uint4*>(&sBlo[o])     = vl;
            *reinterpret_cast<uint4*>(&sBlo[o + 8]) = vl2;
        }
        __syncthreads();

        // --- prefetch next chunk's A while MMAing this one ---
        if (k0 + GBK < IN_F) {
            #pragma unroll
            for (int q = 0; q < 4; q++)
                pf[q] = aval ? *reinterpret_cast<const float4*>(aptr + (k0 + GBK) + q * 4)
                             : make_float4(0.f, 0.f, 0.f, 0.f);
        }

        // --- MMA over the 32-wide chunk, two k-steps of 16 ---
        #pragma unroll
        for (int ks = 0; ks < GBK; ks += 16) {
            unsigned a_hi[2][4], a_lo[2][4];
            #pragma unroll
            for (int mt = 0; mt < 2; mt++) {
                int row = wm * 32 + mt * 16 + (lane & 15);
                int col = ks + ((lane >> 4) << 3);
                unsigned off = (unsigned)(row * SPAD + col) * 2u;
                ldsm_x4(a_hi[mt], uAhi + off);
                ldsm_x4(a_lo[mt], uAlo + off);
            }
            #pragma unroll
            for (int nt = 0; nt < 8; nt++) {
                int brow = wn * 64 + nt * 8 + (lane & 7);
                int bcol = ks + (lane & 8);
                unsigned off = (unsigned)(brow * SPAD + bcol) * 2u;
                unsigned b_hi[2], b_lo[2];
                ldsm_x2(b_hi, uBhi + off);
                ldsm_x2(b_lo, uBlo + off);
                #pragma unroll
                for (int mt = 0; mt < 2; mt++) {
                    mma_bf16(acc[mt][nt], a_hi[mt], b_hi);
                    mma_bf16(acc[mt][nt], a_hi[mt], b_lo);
                    mma_bf16(acc[mt][nt], a_lo[mt], b_hi);
                }
            }
        }
        __syncthreads();
    }

    // --- epilogue ---
    const int g   = lane >> 2;
    const int tig = lane & 3;
    #pragma unroll
    for (int mt = 0; mt < 2; mt++) {
        #pragma unroll
        for (int nt = 0; nt < 8; nt++) {
            int row0 = rowBase + wm * 32 + mt * 16 + g;
            int col  = wn * 64 + nt * 8 + tig * 2;
            if (row0 < M)
                *reinterpret_cast<float2*>(z + (size_t)row0 * OUT_F + col) =
                    make_float2(acc[mt][nt][0], acc[mt][nt][1]);
            int row1 = row0 + 8;
            if (row1 < M)
                *reinterpret_cast<float2*>(z + (size_t)row1 * OUT_F + col) =
                    make_float2(acc[mt][nt][2], acc[mt][nt][3]);
        }
    }
}

// ---------------------------------------------------------------------------
extern "C" void kernel_launch(void* const* d_in, const int* in_sizes, int n_in,
                              void* d_out, int out_size) {
    const float* h   = (const float*)d_in[0];
    const float* W   = (const float*)d_in[1];
    const void*  src = d_in[2];
    const void*  dst = d_in[3];
    float* out = (float*)d_out;

    const int M = in_sizes[0] / IN_F;      // 100000
    const int E = in_sizes[2];             // 1600000

    float* z;
    cudaGetSymbolAddress((void**)&z, g_z);

    const int scan_blocks = (M + SCAN_BLK - 1) / SCAN_BLK;   // 98
    const int eb = (E + 255) / 256;                          // 6250

    // Launch order puts gemm_tc at capture index 3 (profiler samples launch #3).
    prep_kernel<<<(M + 255) / 256, 256>>>((const unsigned long long*)src, E, W, M);  // 0
    hist_kernel<<<eb, 256>>>(dst, E, M);                                             // 1
    scan1_kernel<<<scan_blocks, SCAN_BLK>>>(M);                                      // 2
    gemm_tc_kernel<<<(M + 127) / 128, 256>>>(h, z, M);                               // 3
    scan2_kernel<<<1, 1>>>(scan_blocks);                                             // 4
    scan3_kernel<<<scan_blocks, SCAN_BLK>>>(M);                                      // 5
    fill_kernel<<<eb, 256>>>(src, dst, E, M);                                        // 6

    {
        long long threads = (long long)M * 32;
        int blocks = (int)((threads + 255) / 256);   // 12500
        gather_kernel<<<blocks, 256>>>(z, out, M);                                   // 7
    }
}

// round 6
// speedup vs baseline: 2.3676x; 1.1151x over previous
#include <cuda_runtime.h>
#include <cuda_bf16.h>
#include <cstdint>

// GCN layer: out = segment_mean( (h @ W^T)[src], dst )
//   h   [N=100000, IN=256] f32
//   W   [OUT=128, IN=256]  f32
//   src/dst [E=1600000] indices (int32 or int64 on device; detected at runtime)

#define IN_F  256
#define OUT_F 128
#define MAX_NODES 100000
#define MAX_EDGES 1600000
#define SCAN_BLK  1024

// Scratch (static device globals — no runtime allocation allowed)
__device__ float    g_z[(size_t)MAX_NODES * OUT_F];
__device__ int      g_count[MAX_NODES];
__device__ int      g_off[MAX_NODES];
__device__ int      g_cur[MAX_NODES];
__device__ int      g_srcs[MAX_EDGES];
__device__ int      g_blksum[(MAX_NODES + SCAN_BLK - 1) / SCAN_BLK + 1];
__device__ int      g_idx_is64;
__device__ unsigned g_Whi[OUT_F * IN_F / 2];   // W bf16 hi plane (packed x2)
__device__ unsigned g_Wlo[OUT_F * IN_F / 2];   // W bf16 lo plane (packed x2)

// ---------------------------------------------------------------------------
__device__ __forceinline__ void split4(float4 v, uint2& hi, uint2& lo) {
    unsigned hxy, hzw;
    asm("cvt.rn.bf16x2.f32 %0, %1, %2;" : "=r"(hxy) : "f"(v.y), "f"(v.x));
    asm("cvt.rn.bf16x2.f32 %0, %1, %2;" : "=r"(hzw) : "f"(v.w), "f"(v.z));
    float hx = __uint_as_float(hxy << 16);
    float hy = __uint_as_float(hxy & 0xFFFF0000u);
    float hz = __uint_as_float(hzw << 16);
    float hw = __uint_as_float(hzw & 0xFFFF0000u);
    unsigned lxy, lzw;
    asm("cvt.rn.bf16x2.f32 %0, %1, %2;" : "=r"(lxy) : "f"(v.y - hy), "f"(v.x - hx));
    asm("cvt.rn.bf16x2.f32 %0, %1, %2;" : "=r"(lzw) : "f"(v.w - hw), "f"(v.z - hz));
    hi = make_uint2(hxy, hzw);
    lo = make_uint2(lxy, lzw);
}

// ---------------------------------------------------------------------------
// prep: fused index-dtype detect + counter zero + W split-convert
// ---------------------------------------------------------------------------
__global__ __launch_bounds__(256)
void prep_kernel(const unsigned long long* __restrict__ s64, int E,
                 const float* __restrict__ W, int M) {
    int i = blockIdx.x * blockDim.x + threadIdx.x;
    if (i == 0) {
        int n = E < 16 ? E : 16;
        int is64 = 1;
        for (int j = 0; j < n; j++)
            if ((s64[j] >> 32) != 0ull) { is64 = 0; break; }
        g_idx_is64 = is64;
    }
    if (i < M) { g_count[i] = 0; g_cur[i] = 0; }
    if (i < OUT_F * IN_F / 4) {
        float4 v = *reinterpret_cast<const float4*>(W + (size_t)i * 4);
        uint2 hi, lo;
        split4(v, hi, lo);
        *reinterpret_cast<uint2*>(&g_Whi[i * 2]) = hi;
        *reinterpret_cast<uint2*>(&g_Wlo[i * 2]) = lo;
    }
}

__device__ __forceinline__ int load_idx(const void* p, int i) {
    if (g_idx_is64) return (int)((const long long*)p)[i];
    return ((const int*)p)[i];
}

__global__ __launch_bounds__(256)
void hist_kernel(const void* __restrict__ dst, int E, int M) {
    int e = blockIdx.x * blockDim.x + threadIdx.x;
    if (e >= E) return;
    int d = load_idx(dst, e);
    if ((unsigned)d < (unsigned)M) atomicAdd(&g_count[d], 1);
}

__global__ __launch_bounds__(SCAN_BLK)
void scan1_kernel(int n) {
    __shared__ int sh[SCAN_BLK];
    int gid = blockIdx.x * SCAN_BLK + threadIdx.x;
    int v = (gid < n) ? g_count[gid] : 0;
    sh[threadIdx.x] = v;
    __syncthreads();
    #pragma unroll
    for (int s = 1; s < SCAN_BLK; s <<= 1) {
        int t = (threadIdx.x >= s) ? sh[threadIdx.x - s] : 0;
        __syncthreads();
        sh[threadIdx.x] += t;
        __syncthreads();
    }
    if (gid < n) g_off[gid] = sh[threadIdx.x] - v;
    if (threadIdx.x == SCAN_BLK - 1) g_blksum[blockIdx.x] = sh[threadIdx.x];
}

__global__ void scan2_kernel(int nblocks) {
    int run = 0;
    for (int i = 0; i < nblocks; i++) {
        int v = g_blksum[i];
        g_blksum[i] = run;
        run += v;
    }
}

__global__ __launch_bounds__(SCAN_BLK)
void scan3_kernel(int n) {
    int gid = blockIdx.x * SCAN_BLK + threadIdx.x;
    if (gid < n) g_off[gid] += g_blksum[blockIdx.x];
}

__global__ __launch_bounds__(256)
void fill_kernel(const void* __restrict__ src, const void* __restrict__ dst,
                 int E, int M) {
    int e = blockIdx.x * blockDim.x + threadIdx.x;
    if (e >= E) return;
    int s = load_idx(src, e);
    int d = load_idx(dst, e);
    if ((unsigned)s >= (unsigned)M || (unsigned)d >= (unsigned)M) return;
    int slot = g_off[d] + atomicAdd(&g_cur[d], 1);
    g_srcs[slot] = s;
}

// ---------------------------------------------------------------------------
// Pull-aggregate: one warp per dst node (proven R2-R5).
// ---------------------------------------------------------------------------
__global__ __launch_bounds__(256)
void gather_kernel(const float* __restrict__ z, float* __restrict__ out, int M) {
    int gtid = blockIdx.x * blockDim.x + threadIdx.x;
    int node = gtid >> 5;
    int lane = gtid & 31;
    if (node >= M) return;

    int beg = g_off[node];
    int cnt = g_count[node];

    float4 acc0 = make_float4(0.f, 0.f, 0.f, 0.f);
    float4 acc1 = make_float4(0.f, 0.f, 0.f, 0.f);

    int i = 0;
    for (; i + 2 <= cnt; i += 2) {
        int s0 = g_srcs[beg + i];
        int s1 = g_srcs[beg + i + 1];
        float4 v0 = *reinterpret_cast<const float4*>(z + (size_t)s0 * OUT_F + lane * 4);
        float4 v1 = *reinterpret_cast<const float4*>(z + (size_t)s1 * OUT_F + lane * 4);
        acc0.x += v0.x; acc0.y += v0.y; acc0.z += v0.z; acc0.w += v0.w;
        acc1.x += v1.x; acc1.y += v1.y; acc1.z += v1.z; acc1.w += v1.w;
    }
    if (i < cnt) {
        int s0 = g_srcs[beg + i];
        float4 v0 = *reinterpret_cast<const float4*>(z + (size_t)s0 * OUT_F + lane * 4);
        acc0.x += v0.x; acc0.y += v0.y; acc0.z += v0.z; acc0.w += v0.w;
    }

    float inv = 1.0f / (float)(cnt > 0 ? cnt : 1);
    float4 r;
    r.x = (acc0.x + acc1.x) * inv;
    r.y = (acc0.y + acc1.y) * inv;
    r.z = (acc0.z + acc1.z) * inv;
    r.w = (acc0.w + acc1.w) * inv;
    *reinterpret_cast<float4*>(out + (size_t)node * OUT_F + lane * 4) = r;
}

// ---------------------------------------------------------------------------
// Tensor-core GEMM, double-buffered. Block 128x128, 8 warps (4x2),
// warp tile 32x64, K-chunk 32. Dynamic smem: 2 stages x 4 planes x 10240B.
// Per chunk: cp.async next-B + LDG next-A BEFORE the MMAs; split+STS next-A
// AFTER the MMAs; one __syncthreads per chunk. 2 CTAs/SM via launch_bounds.
// ---------------------------------------------------------------------------
#define GBK 32
#define SPAD 40                       // padded bf16 row stride (elements)
#define PLANE (128 * SPAD * 2)        // 10240 bytes
#define STAGE (4 * PLANE)             // 40960 bytes
#define OFF_AHI 0
#define OFF_ALO PLANE
#define OFF_BHI (2 * PLANE)
#define OFF_BLO (3 * PLANE)

__device__ __forceinline__ void ldsm_x4(unsigned r[4], unsigned saddr) {
    asm volatile("ldmatrix.sync.aligned.m8n8.x4.shared.b16 {%0,%1,%2,%3}, [%4];"
                 : "=r"(r[0]), "=r"(r[1]), "=r"(r[2]), "=r"(r[3]) : "r"(saddr));
}
__device__ __forceinline__ void ldsm_x2(unsigned r[2], unsigned saddr) {
    asm volatile("ldmatrix.sync.aligned.m8n8.x2.shared.b16 {%0,%1}, [%2];"
                 : "=r"(r[0]), "=r"(r[1]) : "r"(saddr));
}
__device__ __forceinline__ void mma_bf16(float c[4], const unsigned a[4],
                                         const unsigned b[2]) {
    asm volatile("mma.sync.aligned.m16n8k16.row.col.f32.bf16.bf16.f32 "
                 "{%0,%1,%2,%3}, {%4,%5,%6,%7}, {%8,%9}, {%0,%1,%2,%3};"
                 : "+f"(c[0]), "+f"(c[1]), "+f"(c[2]), "+f"(c[3])
                 : "r"(a[0]), "r"(a[1]), "r"(a[2]), "r"(a[3]),
                   "r"(b[0]), "r"(b[1]));
}
__device__ __forceinline__ void cp16(unsigned sdst, const void* gsrc) {
    asm volatile("cp.async.cg.shared.global [%0], [%1], 16;"
                 :: "r"(sdst), "l"(gsrc));
}
__device__ __forceinline__ void cp_commit() {
    asm volatile("cp.async.commit_group;");
}
__device__ __forceinline__ void cp_wait0() {
    asm volatile("cp.async.wait_group 0;");
}

__global__ __launch_bounds__(256, 2)
void gemm_tc_kernel(const float* __restrict__ h, float* __restrict__ z, int M) {
    extern __shared__ __align__(16) char dyn[];
    const unsigned uDyn = (unsigned)__cvta_generic_to_shared(dyn);

    const int tid  = threadIdx.x;
    const int warp = tid >> 5;
    const int lane = tid & 31;
    const int wm   = warp & 3;
    const int wn   = warp >> 2;
    const int rowBase = blockIdx.x * 128;

    // A staging map: rows 0..127, two threads per row, 16 cols each (4 float4)
    const int ar = tid >> 1;
    const int ac = (tid & 1) * 16;
    const bool aval = (rowBase + ar) < M;
    const float* aptr = h + (size_t)(rowBase + ar) * IN_F + ac;

    // B staging map: row br, word cols [k0/2 + bc, +8)
    const int br = tid >> 1;
    const int bc = (tid & 1) * 8;
    const unsigned bSmemOff = (unsigned)(br * SPAD + bc * 2) * 2u;  // bytes

    float acc[2][8][4] = {};
    float4 pf[4];

    // ---- prologue: stage chunk 0 into buffer 0 ----
    {
        const unsigned sb = uDyn;
        cp16(sb + OFF_BHI + bSmemOff,      &g_Whi[(size_t)br * (IN_F / 2) + bc]);
        cp16(sb + OFF_BHI + bSmemOff + 16, &g_Whi[(size_t)br * (IN_F / 2) + bc + 4]);
        cp16(sb + OFF_BLO + bSmemOff,      &g_Wlo[(size_t)br * (IN_F / 2) + bc]);
        cp16(sb + OFF_BLO + bSmemOff + 16, &g_Wlo[(size_t)br * (IN_F / 2) + bc + 4]);
        cp_commit();
        #pragma unroll
        for (int q = 0; q < 4; q++)
            pf[q] = aval ? *reinterpret_cast<const float4*>(aptr + q * 4)
                         : make_float4(0.f, 0.f, 0.f, 0.f);
        char* ab = dyn;
        #pragma unroll
        for (int q = 0; q < 4; q++) {
            uint2 hi, lo;
            split4(pf[q], hi, lo);
            int o = (ar * SPAD + ac + q * 4) * 2;
            *reinterpret_cast<uint2*>(ab + OFF_AHI + o) = hi;
            *reinterpret_cast<uint2*>(ab + OFF_ALO + o) = lo;
        }
        cp_wait0();
        __syncthreads();
    }

    const int NCHUNK = IN_F / GBK;   // 8
    for (int c = 0; c < NCHUNK; c++) {
        const int buf  = c & 1;
        const int nbuf = buf ^ 1;
        const unsigned sb  = uDyn + buf * STAGE;
        const unsigned snb = uDyn + nbuf * STAGE;
        const bool has_next = (c + 1 < NCHUNK);

        // issue next-chunk loads before MMAs (independent of MMA inputs)
        if (has_next) {
            const int k0n = (c + 1) * GBK;
            cp16(snb + OFF_BHI + bSmemOff,      &g_Whi[(size_t)br * (IN_F / 2) + k0n / 2 + bc]);
            cp16(snb + OFF_BHI + bSmemOff + 16, &g_Whi[(size_t)br * (IN_F / 2) + k0n / 2 + bc + 4]);
            cp16(snb + OFF_BLO + bSmemOff,      &g_Wlo[(size_t)br * (IN_F / 2) + k0n / 2 + bc]);
            cp16(snb + OFF_BLO + bSmemOff + 16, &g_Wlo[(size_t)br * (IN_F / 2) + k0n / 2 + bc + 4]);
            cp_commit();
            #pragma unroll
            for (int q = 0; q < 4; q++)
                pf[q] = aval ? *reinterpret_cast<const float4*>(aptr + k0n + q * 4)
                             : make_float4(0.f, 0.f, 0.f, 0.f);
        }

        // ---- MMAs on current buffer ----
        #pragma unroll
        for (int ks = 0; ks < GBK; ks += 16) {
            unsigned a_hi[2][4], a_lo[2][4];
            #pragma unroll
            for (int mt = 0; mt < 2; mt++) {
                int row = wm * 32 + mt * 16 + (lane & 15);
                int col = ks + ((lane >> 4) << 3);
                unsigned off = (unsigned)(row * SPAD + col) * 2u;
                ldsm_x4(a_hi[mt], sb + OFF_AHI + off);
                ldsm_x4(a_lo[mt], sb + OFF_ALO + off);
            }
            #pragma unroll
            for (int nt = 0; nt < 8; nt++) {
                int brow = wn * 64 + nt * 8 + (lane & 7);
                int bcol = ks + (lane & 8);
                unsigned off = (unsigned)(brow * SPAD + bcol) * 2u;
                unsigned b_hi[2], b_lo[2];
                ldsm_x2(b_hi, sb + OFF_BHI + off);
                ldsm_x2(b_lo, sb + OFF_BLO + off);
                #pragma unroll
                for (int mt = 0; mt < 2; mt++) {
                    mma_bf16(acc[mt][nt], a_hi[mt], b_hi);
                    mma_bf16(acc[mt][nt], a_hi[mt], b_lo);
                    mma_bf16(acc[mt][nt], a_lo[mt], b_hi);
                }
            }
        }

        // split+store next A (LDGs have landed behind the MMA block)
        if (has_next) {
            char* ab = dyn + nbuf * STAGE;
            #pragma unroll
            for (int q = 0; q < 4; q++) {
                uint2 hi, lo;
                split4(pf[q], hi, lo);
                int o = (ar * SPAD + ac + q * 4) * 2;
                *reinterpret_cast<uint2*>(ab + OFF_AHI + o) = hi;
                *reinterpret_cast<uint2*>(ab + OFF_ALO + o) = lo;
            }
            cp_wait0();
        }
        __syncthreads();
    }

    // ---- epilogue ----
    const int g   = lane >> 2;
    const int tig = lane & 3;
    #pragma unroll
    for (int mt = 0; mt < 2; mt++) {
        #pragma unroll
        for (int nt = 0; nt < 8; nt++) {
            int row0 = rowBase + wm * 32 + mt * 16 + g;
            int col  = wn * 64 + nt * 8 + tig * 2;
            if (row0 < M)
                *reinterpret_cast<float2*>(z + (size_t)row0 * OUT_F + col) =
                    make_float2(acc[mt][nt][0], acc[mt][nt][1]);
            int row1 = row0 + 8;
            if (row1 < M)
                *reinterpret_cast<float2*>(z + (size_t)row1 * OUT_F + col) =
                    make_float2(acc[mt][nt][2], acc[mt][nt][3]);
        }
    }
}

// ---------------------------------------------------------------------------
extern "C" void kernel_launch(void* const* d_in, const int* in_sizes, int n_in,
                              void* d_out, int out_size) {
    const float* h   = (const float*)d_in[0];
    const float* W   = (const float*)d_in[1];
    const void*  src = d_in[2];
    const void*  dst = d_in[3];
    float* out = (float*)d_out;

    const int M = in_sizes[0] / IN_F;      // 100000
    const int E = in_sizes[2];             // 1600000

    float* z;
    cudaGetSymbolAddress((void**)&z, g_z);

    const int scan_blocks = (M + SCAN_BLK - 1) / SCAN_BLK;   // 98
    const int eb = (E + 255) / 256;                          // 6250
    const int dynBytes = 2 * STAGE;                          // 81920

    cudaFuncSetAttribute(gemm_tc_kernel,
                         cudaFuncAttributeMaxDynamicSharedMemorySize, dynBytes);

    // gemm_tc stays at capture index 3 (profiler samples launch #3).
    prep_kernel<<<(M + 255) / 256, 256>>>((const unsigned long long*)src, E, W, M);  // 0
    hist_kernel<<<eb, 256>>>(dst, E, M);                                             // 1
    scan1_kernel<<<scan_blocks, SCAN_BLK>>>(M);                                      // 2
    gemm_tc_kernel<<<(M + 127) / 128, 256, dynBytes>>>(h, z, M);                     // 3
    scan2_kernel<<<1, 1>>>(scan_blocks);                                             // 4
    scan3_kernel<<<scan_blocks, SCAN_BLK>>>(M);                                      // 5
    fill_kernel<<<eb, 256>>>(src, dst, E, M);                                        // 6

    {
        long long threads = (long long)M * 32;
        int blocks = (int)((threads + 255) / 256);   // 12500
        gather_kernel<<<blocks, 256>>>(z, out, M);                                   // 7
    }
}